// round 6
// baseline (speedup 1.0000x reference)
#include <cuda_runtime.h>

#define BATCH     16384
#define QSEQ      1204
#define FDIM      7
#define NCHUNKS   120
#define NOFF      5
#define WINSZ     10
#define NCAT      600
#define H1DIM     128
#define H2DIM     32
#define ODIM      2

// cat scratch, k-major, every value DUPLICATED as a float2 pair:
//   g_cat2[k*BATCH + b] = (cat[b][k], cat[b][k])
__device__ float2 g_cat2[(size_t)NCAT * BATCH];

// ---------------------------------------------------------------------------
// f32x2 helpers
// ---------------------------------------------------------------------------
__device__ __forceinline__ void unpack2(unsigned long long v, float& lo, float& hi) {
    asm("mov.b64 {%0, %1}, %2;" : "=f"(lo), "=f"(hi) : "l"(v));
}
__device__ __forceinline__ unsigned long long ffma2(unsigned long long a,
                                                    unsigned long long b,
                                                    unsigned long long c) {
    unsigned long long d;
    asm("fma.rn.f32x2 %0, %1, %2, %3;" : "=l"(d) : "l"(a), "l"(b), "l"(c));
    return d;
}

__device__ __forceinline__ void cp_async16(void* smem_dst, const void* gsrc) {
    unsigned s = (unsigned)__cvta_generic_to_shared(smem_dst);
    asm volatile("cp.async.ca.shared.global [%0], [%1], 16;\n" :: "r"(s), "l"(gsrc));
}
__device__ __forceinline__ void cp_commit() {
    asm volatile("cp.async.commit_group;\n" ::: "memory");
}
__device__ __forceinline__ void cp_wait0() {
    asm volatile("cp.async.wait_group 0;\n" ::: "memory");
}

// ===========================================================================
// Kernel 1: dot-7 + windowed max pool. Barrier-free, smem-free streaming.
// Thread = (chunk i = gid>>14, row r = gid&16383). Reads 98 floats (8B aligned),
// computes 14 dots, 21-max decomposition, writes 5 duplicated float2 values.
// ===========================================================================
__global__ __launch_bounds__(256)
void pool_kernel(const float* __restrict__ x,
                 const float* __restrict__ w_step,
                 const float* __restrict__ b_step)
{
    const unsigned gid = blockIdx.x * 256u + threadIdx.x;
    const int r = gid & (BATCH - 1);
    const int i = gid >> 14;            // 0..119

    float ws[FDIM];
#pragma unroll
    for (int f = 0; f < FDIM; ++f) ws[f] = __ldg(&w_step[f]);
    const float bs = __ldg(b_step);

    // base: x[r][i*10 .. i*10+14) * 7 floats  ->  floats [70i, 70i+98)
    const float2* p = (const float2*)(x + (size_t)r * (QSEQ * FDIM) + i * 70);

    float d[14];

    // phase A: floats 0..48 -> positions 0..6   (buf covers floats 0..49)
    {
        float2 buf[25];
#pragma unroll
        for (int t = 0; t < 25; ++t) buf[t] = p[t];
#pragma unroll
        for (int j = 0; j < 7; ++j) {
            float acc = bs;
#pragma unroll
            for (int f = 0; f < FDIM; ++f) {
                const int idx = 7 * j + f;
                const float v = (idx & 1) ? buf[idx >> 1].y : buf[idx >> 1].x;
                acc = fmaf(v, ws[f], acc);
            }
            d[j] = acc;
        }
    }
    // phase B: floats 48..97 -> positions 7..13 (buf covers floats 48..97)
    {
        float2 buf[25];
#pragma unroll
        for (int t = 0; t < 25; ++t) buf[t] = p[24 + t];
#pragma unroll
        for (int j = 7; j < 14; ++j) {
            float acc = bs;
#pragma unroll
            for (int f = 0; f < FDIM; ++f) {
                const int idx = 7 * j + f - 48;   // 1..49
                const float v = (idx & 1) ? buf[idx >> 1].y : buf[idx >> 1].x;
                acc = fmaf(v, ws[f], acc);
            }
            d[j] = acc;
        }
    }

    // windowed maxes: window o covers d[o .. o+9], o = 0..4
    float common = d[4];
#pragma unroll
    for (int j = 5; j < 10; ++j) common = fmaxf(common, d[j]);
    const float P1 = d[10];
    const float P2 = fmaxf(P1, d[11]);
    const float P3 = fmaxf(P2, d[12]);
    const float P4 = fmaxf(P3, d[13]);
    const float T3 = d[3];
    const float T2 = fmaxf(d[2], T3);
    const float T1 = fmaxf(d[1], T2);
    const float T0 = fmaxf(d[0], T1);

    float m[5];
    m[0] = fmaxf(common, T0);
    m[1] = fmaxf(fmaxf(common, T1), P1);
    m[2] = fmaxf(fmaxf(common, T2), P2);
    m[3] = fmaxf(fmaxf(common, T3), P3);
    m[4] = fmaxf(common, P4);

    const size_t kbase = (size_t)(i * NOFF) * BATCH + r;
#pragma unroll
    for (int o = 0; o < NOFF; ++o) {
        float2 v; v.x = m[o]; v.y = m[o];
        g_cat2[kbase + (size_t)o * BATCH] = v;    // coalesced ST.64 across warp
    }
}

// ===========================================================================
// Kernel 2: MLP. 128 thr/CTA, 32 rows/CTA (grid 512).
// Double-buffered {wA k-tile + duplicated-cat k-tile}; 8 neurons x 4 rows per
// thread; inner loop = 4 LDS.128 + 16 FFMA2, zero packing movs.
// ===========================================================================
#define NROWS  32
#define KT     24
#define NTILE  25                       // 25*24 = 600
#define WA_TF  (KT * H1DIM)             // 3072 floats
#define CT_TF  (KT * NROWS * 2)         // 1536 floats (duplicated)
#define BUF_F  (WA_TF + CT_TF)          // 4608 floats per buffer
#define SM_F   (2 * BUF_F)              // 9216 floats = 36864 B
#define SM_BYTES (SM_F * 4)

__global__ __launch_bounds__(128)
void mlp_kernel(const float* __restrict__ wA,
                const float* __restrict__ bA,
                const float* __restrict__ wB,
                const float* __restrict__ bB,
                const float* __restrict__ wC,
                const float* __restrict__ bC,
                float* __restrict__ out)
{
    extern __shared__ float smem[];
    // buffers: buf b at smem + b*BUF_F ; wA at +0, cat2 at +WA_TF
    float* sm_h1 = smem;                // 4096 floats, alias after loop
    float* sm_h2 = smem + H1DIM * NROWS; // 1024 floats

    const int tid = threadIdx.x;
    const size_t b0 = (size_t)blockIdx.x * NROWS;

    const int jq = tid & 15;            // neuron oct: j0 = 8*jq
    const int rs = tid >> 4;            // row quad:  r0 = 4*rs
    const int j0 = jq * 8;
    const int r0 = rs * 4;

    // ---- prologue: tile 0 (wA + cat2) in one group ----
    {
        float* wbuf = smem;
        float* cbuf = smem + WA_TF;
#pragma unroll
        for (int j = 0; j < 6; ++j) {
            const int idx = tid + j * 128;          // 0..767 float4s
            cp_async16(wbuf + idx * 4, wA + idx * 4);
        }
#pragma unroll
        for (int j = 0; j < 3; ++j) {
            const int idx = tid + j * 128;          // 0..383 16B-chunks
            const int kk = idx >> 4;
            const int rp = idx & 15;                // row pair
            cp_async16(cbuf + kk * (NROWS * 2) + rp * 4,
                       &g_cat2[(size_t)kk * BATCH + b0 + rp * 2]);
        }
        cp_commit();
    }

    // acc[np][r]: neuron pair (j0+2np, j0+2np+1), row r0+r
    unsigned long long acc[4][4];
#pragma unroll
    for (int n = 0; n < 4; ++n)
#pragma unroll
        for (int r = 0; r < 4; ++r) acc[n][r] = 0ULL;

    for (int t = 0; t < NTILE; ++t) {
        cp_wait0();
        __syncthreads();
        if (t + 1 < NTILE) {
            float* wbuf = smem + ((t + 1) & 1) * BUF_F;
            float* cbuf = wbuf + WA_TF;
            const float* wsrc = wA + (size_t)(t + 1) * WA_TF;
            const size_t kof = (size_t)(t + 1) * KT;
#pragma unroll
            for (int j = 0; j < 6; ++j) {
                const int idx = tid + j * 128;
                cp_async16(wbuf + idx * 4, wsrc + idx * 4);
            }
#pragma unroll
            for (int j = 0; j < 3; ++j) {
                const int idx = tid + j * 128;
                const int kk = idx >> 4;
                const int rp = idx & 15;
                cp_async16(cbuf + kk * (NROWS * 2) + rp * 4,
                           &g_cat2[(kof + kk) * BATCH + b0 + rp * 2]);
            }
            cp_commit();
        }

        const float* wt = smem + (t & 1) * BUF_F + j0;
        const float* ct = smem + (t & 1) * BUF_F + WA_TF + r0 * 2;
#pragma unroll 4
        for (int kk = 0; kk < KT; ++kk) {
            const ulonglong2 w0 = *(const ulonglong2*)(wt + kk * H1DIM);       // n 0..3
            const ulonglong2 w1 = *(const ulonglong2*)(wt + kk * H1DIM + 4);   // n 4..7
            const ulonglong2 c0 = *(const ulonglong2*)(ct + kk * (NROWS * 2));     // rows r0,r0+1 (splat)
            const ulonglong2 c1 = *(const ulonglong2*)(ct + kk * (NROWS * 2) + 4); // rows r0+2,r0+3
            acc[0][0] = ffma2(w0.x, c0.x, acc[0][0]);
            acc[1][0] = ffma2(w0.y, c0.x, acc[1][0]);
            acc[2][0] = ffma2(w1.x, c0.x, acc[2][0]);
            acc[3][0] = ffma2(w1.y, c0.x, acc[3][0]);
            acc[0][1] = ffma2(w0.x, c0.y, acc[0][1]);
            acc[1][1] = ffma2(w0.y, c0.y, acc[1][1]);
            acc[2][1] = ffma2(w1.x, c0.y, acc[2][1]);
            acc[3][1] = ffma2(w1.y, c0.y, acc[3][1]);
            acc[0][2] = ffma2(w0.x, c1.x, acc[0][2]);
            acc[1][2] = ffma2(w0.y, c1.x, acc[1][2]);
            acc[2][2] = ffma2(w1.x, c1.x, acc[2][2]);
            acc[3][2] = ffma2(w1.y, c1.x, acc[3][2]);
            acc[0][3] = ffma2(w0.x, c1.y, acc[0][3]);
            acc[1][3] = ffma2(w0.y, c1.y, acc[1][3]);
            acc[2][3] = ffma2(w1.x, c1.y, acc[2][3]);
            acc[3][3] = ffma2(w1.y, c1.y, acc[3][3]);
        }
    }

    const float4 ba0 = *(const float4*)&bA[j0];
    const float4 ba1 = *(const float4*)&bA[j0 + 4];
    __syncthreads();   // all buffer reads done; safe to alias h1

    // ---- epilogue: h1[j*32 + r] = relu(acc + bias) ----
    {
        const float bb[8] = {ba0.x, ba0.y, ba0.z, ba0.w, ba1.x, ba1.y, ba1.z, ba1.w};
        float lo, hi;
#pragma unroll
        for (int n = 0; n < 4; ++n) {
#pragma unroll
            for (int r = 0; r < 4; ++r) {
                unpack2(acc[n][r], lo, hi);
                sm_h1[(j0 + 2*n + 0) * NROWS + r0 + r] = fmaxf(lo + bb[2*n + 0], 0.0f);
                sm_h1[(j0 + 2*n + 1) * NROWS + r0 + r] = fmaxf(hi + bb[2*n + 1], 0.0f);
            }
        }
    }
    __syncthreads();

    // ---- Layer B: h2[r][m] = relu(sum_j h1[j][r]*wB[j][m] + bB[m]) ----
    {
        const int m  = tid & 31;
        const int rb = (tid >> 5) * 8;           // 8 rows per thread
        float s[8];
#pragma unroll
        for (int r = 0; r < 8; ++r) s[r] = 0.0f;
#pragma unroll 4
        for (int j = 0; j < H1DIM; ++j) {
            const float wb = __ldg(&wB[j * H2DIM + m]);
            const float4 h0 = *(const float4*)&sm_h1[j * NROWS + rb];
            const float4 h1v = *(const float4*)&sm_h1[j * NROWS + rb + 4];
            s[0] = fmaf(h0.x, wb, s[0]);
            s[1] = fmaf(h0.y, wb, s[1]);
            s[2] = fmaf(h0.z, wb, s[2]);
            s[3] = fmaf(h0.w, wb, s[3]);
            s[4] = fmaf(h1v.x, wb, s[4]);
            s[5] = fmaf(h1v.y, wb, s[5]);
            s[6] = fmaf(h1v.z, wb, s[6]);
            s[7] = fmaf(h1v.w, wb, s[7]);
        }
        const float bm = __ldg(&bB[m]);
        __syncthreads();   // h1 reads done before... (h2 is separate region, but keep order)
#pragma unroll
        for (int r = 0; r < 8; ++r)
            sm_h2[(rb + r) * H2DIM + m] = fmaxf(s[r] + bm, 0.0f);
    }
    __syncthreads();

    // ---- Layer C ----
    if (tid < NROWS * ODIM) {
        const int r = tid >> 1;
        const int c = tid & 1;
        float s = __ldg(&bC[c]);
#pragma unroll
        for (int m = 0; m < H2DIM; ++m)
            s = fmaf(sm_h2[r * H2DIM + m], __ldg(&wC[m * ODIM + c]), s);
        out[(b0 + (size_t)r) * ODIM + c] = s;
    }
}

extern "C" void kernel_launch(void* const* d_in, const int* in_sizes, int n_in,
                              void* d_out, int out_size)
{
    const float* x      = (const float*)d_in[0];
    const float* w_step = (const float*)d_in[1];
    const float* b_step = (const float*)d_in[2];
    const float* wA     = (const float*)d_in[3];
    const float* bA     = (const float*)d_in[4];
    const float* wB     = (const float*)d_in[5];
    const float* bB     = (const float*)d_in[6];
    const float* wC     = (const float*)d_in[7];
    const float* bC     = (const float*)d_in[8];
    float* out          = (float*)d_out;

    cudaFuncSetAttribute(mlp_kernel, cudaFuncAttributeMaxDynamicSharedMemorySize, SM_BYTES);

    pool_kernel<<<(NCHUNKS * BATCH) / 256, 256>>>(x, w_step, b_step);
    mlp_kernel<<<BATCH / NROWS, 128, SM_BYTES>>>(wA, bA, wB, bB, wC, bC, out);
}

// round 7
// speedup vs baseline: 1.1628x; 1.1628x over previous
#include <cuda_runtime.h>

#define BATCH     16384
#define QSEQ      1204
#define FDIM      7
#define NCHUNKS   120
#define NOFF      5
#define WINSZ     10
#define NCAT      600
#define H1DIM     128
#define H2DIM     32
#define ODIM      2

// cat scratch, k-major, each value duplicated: g_cat2[k*BATCH + b] = (v, v)
__device__ float2 g_cat2[(size_t)NCAT * BATCH];
// layer-A partials: [khalf][rowgroup][r][j]  (pre-bias, pre-relu)
__device__ float g_part[2][512][32][128];

// ---------------------------------------------------------------------------
__device__ __forceinline__ unsigned long long ffma2(unsigned long long a,
                                                    unsigned long long b,
                                                    unsigned long long c) {
    unsigned long long d;
    asm("fma.rn.f32x2 %0, %1, %2, %3;" : "=l"(d) : "l"(a), "l"(b), "l"(c));
    return d;
}
__device__ __forceinline__ void cp_async16(void* smem_dst, const void* gsrc) {
    unsigned s = (unsigned)__cvta_generic_to_shared(smem_dst);
    asm volatile("cp.async.ca.shared.global [%0], [%1], 16;\n" :: "r"(s), "l"(gsrc));
}
__device__ __forceinline__ void cp_commit() {
    asm volatile("cp.async.commit_group;\n" ::: "memory");
}
__device__ __forceinline__ void cp_wait0() {
    asm volatile("cp.async.wait_group 0;\n" ::: "memory");
}

// ===========================================================================
// Kernel 1: dot-7 + windowed max pool (R5 design: smem-staged, coalesced)
// ===========================================================================
#define K1_ROWS 8
__global__ __launch_bounds__(256)
void pool_kernel(const float* __restrict__ x,
                 const float* __restrict__ w_step,
                 const float* __restrict__ b_step)
{
    __shared__ float sm_out[K1_ROWS][QSEQ];

    const int tid = threadIdx.x;
    const size_t b0 = (size_t)blockIdx.x * K1_ROWS;

    float ws[FDIM];
#pragma unroll
    for (int f = 0; f < FDIM; ++f) ws[f] = __ldg(&w_step[f]);
    const float bs = __ldg(b_step);

    for (int it = tid; it < K1_ROWS * 301; it += 256) {
        const int r  = it / 301;
        const int qd = it - r * 301;
        const float4* p = (const float4*)(x + (b0 + (size_t)r) * (QSEQ * FDIM) + qd * 28);
        float v[28];
#pragma unroll
        for (int i = 0; i < 7; ++i) {
            float4 t = p[i];
            v[i*4+0] = t.x; v[i*4+1] = t.y; v[i*4+2] = t.z; v[i*4+3] = t.w;
        }
#pragma unroll
        for (int qq = 0; qq < 4; ++qq) {
            float acc = bs;
#pragma unroll
            for (int f = 0; f < FDIM; ++f)
                acc = fmaf(v[qq*FDIM + f], ws[f], acc);
            sm_out[r][qd*4 + qq] = acc;
        }
    }
    __syncthreads();

    for (int it = tid; it < K1_ROWS * NCHUNKS; it += 256) {
        const int r = it & (K1_ROWS - 1);
        const int i = it >> 3;
        const float* o = &sm_out[r][i * WINSZ];
        float v[14];
#pragma unroll
        for (int j = 0; j < 14; ++j) v[j] = o[j];

        float common = v[4];
#pragma unroll
        for (int j = 5; j < 10; ++j) common = fmaxf(common, v[j]);
        const float P1 = v[10];
        const float P2 = fmaxf(P1, v[11]);
        const float P3 = fmaxf(P2, v[12]);
        const float P4 = fmaxf(P3, v[13]);
        const float T3 = v[3];
        const float T2 = fmaxf(v[2], T3);
        const float T1 = fmaxf(v[1], T2);
        const float T0 = fmaxf(v[0], T1);

        float m[5];
        m[0] = fmaxf(common, T0);
        m[1] = fmaxf(fmaxf(common, T1), P1);
        m[2] = fmaxf(fmaxf(common, T2), P2);
        m[3] = fmaxf(fmaxf(common, T3), P3);
        m[4] = fmaxf(common, P4);

        const size_t base = b0 + (size_t)r;
        const size_t c0 = (size_t)(i * NOFF) * BATCH + base;
#pragma unroll
        for (int o2 = 0; o2 < NOFF; ++o2) {
            float2 vv; vv.x = m[o2]; vv.y = m[o2];
            g_cat2[c0 + (size_t)o2 * BATCH] = vv;
        }
    }
}

// ===========================================================================
// Kernel 2a: layer A, split-K x2. grid = 1024 (rg = blk>>1, kh = blk&1).
// 128 thr; thread = 8 neurons x 4 rows; 16 FFMA2 + 4 LDS.128 per k.
// ===========================================================================
#define NROWS  32
#define KHALF  300
#define KT     20
#define NTILE  15                       // 15*20 = 300
#define WA_TF  (KT * H1DIM)             // 2560 floats
#define CT_TF  (KT * NROWS * 2)         // 1280 floats (duplicated)
#define BUF_F  (WA_TF + CT_TF)          // 3840 floats

__global__ __launch_bounds__(128, 7)
void mlpA_kernel(const float* __restrict__ wA)
{
    __shared__ float smem[2 * BUF_F];   // 30720 B

    const int tid = threadIdx.x;
    const int rg  = blockIdx.x >> 1;
    const int kh  = blockIdx.x & 1;
    const size_t b0 = (size_t)rg * NROWS;

    const float* wAh = wA + (size_t)kh * KHALF * H1DIM;
    const size_t kbase = (size_t)kh * KHALF;

    const int jq = tid & 15;            // j0 = 8*jq
    const int rs = tid >> 4;            // r0 = 4*rs
    const int j0 = jq * 8;
    const int r0 = rs * 4;

    // ---- prologue: tile 0 ----
    {
        float* wbuf = smem;
        float* cbuf = smem + WA_TF;
#pragma unroll
        for (int i = 0; i < 5; ++i) {               // 640 float4
            const int idx = tid + i * 128;
            cp_async16(wbuf + idx * 4, wAh + idx * 4);
        }
        for (int idx = tid; idx < 320; idx += 128) { // 320 16B chunks
            const int kk = idx >> 4;
            const int rp = idx & 15;
            cp_async16(cbuf + kk * (NROWS * 2) + rp * 4,
                       &g_cat2[(kbase + kk) * BATCH + b0 + rp * 2]);
        }
        cp_commit();
    }

    unsigned long long acc[4][4];
#pragma unroll
    for (int n = 0; n < 4; ++n)
#pragma unroll
        for (int r = 0; r < 4; ++r) acc[n][r] = 0ULL;

    for (int t = 0; t < NTILE; ++t) {
        cp_wait0();
        __syncthreads();
        if (t + 1 < NTILE) {
            float* wbuf = smem + ((t + 1) & 1) * BUF_F;
            float* cbuf = wbuf + WA_TF;
            const float* wsrc = wAh + (size_t)(t + 1) * WA_TF;
            const size_t kof = kbase + (size_t)(t + 1) * KT;
#pragma unroll
            for (int i = 0; i < 5; ++i) {
                const int idx = tid + i * 128;
                cp_async16(wbuf + idx * 4, wsrc + idx * 4);
            }
            for (int idx = tid; idx < 320; idx += 128) {
                const int kk = idx >> 4;
                const int rp = idx & 15;
                cp_async16(cbuf + kk * (NROWS * 2) + rp * 4,
                           &g_cat2[(kof + kk) * BATCH + b0 + rp * 2]);
            }
            cp_commit();
        }

        const float* wt = smem + (t & 1) * BUF_F + j0;
        const float* ct = smem + (t & 1) * BUF_F + WA_TF + r0 * 2;
#pragma unroll 4
        for (int kk = 0; kk < KT; ++kk) {
            const ulonglong2 w0 = *(const ulonglong2*)(wt + kk * H1DIM);       // neurons j0..j0+3
            const ulonglong2 w1 = *(const ulonglong2*)(wt + kk * H1DIM + 4);   // neurons j0+4..j0+7
            const ulonglong2 c0 = *(const ulonglong2*)(ct + kk * (NROWS * 2));     // rows r0,r0+1 (dup)
            const ulonglong2 c1 = *(const ulonglong2*)(ct + kk * (NROWS * 2) + 4); // rows r0+2,r0+3
            acc[0][0] = ffma2(w0.x, c0.x, acc[0][0]);
            acc[1][0] = ffma2(w0.y, c0.x, acc[1][0]);
            acc[2][0] = ffma2(w1.x, c0.x, acc[2][0]);
            acc[3][0] = ffma2(w1.y, c0.x, acc[3][0]);
            acc[0][1] = ffma2(w0.x, c0.y, acc[0][1]);
            acc[1][1] = ffma2(w0.y, c0.y, acc[1][1]);
            acc[2][1] = ffma2(w1.x, c0.y, acc[2][1]);
            acc[3][1] = ffma2(w1.y, c0.y, acc[3][1]);
            acc[0][2] = ffma2(w0.x, c1.x, acc[0][2]);
            acc[1][2] = ffma2(w0.y, c1.x, acc[1][2]);
            acc[2][2] = ffma2(w1.x, c1.x, acc[2][2]);
            acc[3][2] = ffma2(w1.y, c1.x, acc[3][2]);
            acc[0][3] = ffma2(w0.x, c1.y, acc[0][3]);
            acc[1][3] = ffma2(w0.y, c1.y, acc[1][3]);
            acc[2][3] = ffma2(w1.x, c1.y, acc[2][3]);
            acc[3][3] = ffma2(w1.y, c1.y, acc[3][3]);
        }
    }

    // ---- epilogue: coalesced STG.128 of partials, layout [r][j] ----
    float* dst = &g_part[kh][rg][0][0];
#pragma unroll
    for (int r = 0; r < 4; ++r) {
        ulonglong2 s0, s1;
        s0.x = acc[0][r]; s0.y = acc[1][r];      // j0..j0+3
        s1.x = acc[2][r]; s1.y = acc[3][r];      // j0+4..j0+7
        *(ulonglong2*)&dst[(r0 + r) * H1DIM + j0]     = s0;
        *(ulonglong2*)&dst[(r0 + r) * H1DIM + j0 + 4] = s1;
    }
}

// ===========================================================================
// Kernel 2b: combine halves + bias/relu, then layers B and C.
// ===========================================================================
#define H1PAD 33
__global__ __launch_bounds__(256)
void mlpB_kernel(const float* __restrict__ bA,
                 const float* __restrict__ wB,
                 const float* __restrict__ bB,
                 const float* __restrict__ wC,
                 const float* __restrict__ bC,
                 float* __restrict__ out)
{
    __shared__ float h1[H1DIM * H1PAD];      // [j][r], padded
    __shared__ float h2[NROWS * H2DIM];

    const int tid = threadIdx.x;
    const int rg  = blockIdx.x;
    const size_t b0 = (size_t)rg * NROWS;

    const float* p0 = &g_part[0][rg][0][0];
    const float* p1 = &g_part[1][rg][0][0];

    // sum halves + bias + relu, transpose into h1[j][r]
    for (int idx = tid; idx < (NROWS * H1DIM) / 4; idx += 256) {
        const int r  = idx >> 5;
        const int j4 = (idx & 31) * 4;
        const float4 a  = *(const float4*)&p0[r * H1DIM + j4];
        const float4 b  = *(const float4*)&p1[r * H1DIM + j4];
        const float4 bb = *(const float4*)&bA[j4];
        h1[(j4 + 0) * H1PAD + r] = fmaxf(a.x + b.x + bb.x, 0.0f);
        h1[(j4 + 1) * H1PAD + r] = fmaxf(a.y + b.y + bb.y, 0.0f);
        h1[(j4 + 2) * H1PAD + r] = fmaxf(a.z + b.z + bb.z, 0.0f);
        h1[(j4 + 3) * H1PAD + r] = fmaxf(a.w + b.w + bb.w, 0.0f);
    }
    __syncthreads();

    // layer B: thread = (m, 4 rows)
    {
        const int m  = tid & 31;
        const int rb = (tid >> 5) * 4;
        float s0 = 0, s1 = 0, s2 = 0, s3 = 0;
#pragma unroll 4
        for (int j = 0; j < H1DIM; ++j) {
            const float wb = __ldg(&wB[j * H2DIM + m]);
            const float* hj = &h1[j * H1PAD + rb];
            s0 = fmaf(hj[0], wb, s0);
            s1 = fmaf(hj[1], wb, s1);
            s2 = fmaf(hj[2], wb, s2);
            s3 = fmaf(hj[3], wb, s3);
        }
        const float bm = __ldg(&bB[m]);
        h2[(rb + 0) * H2DIM + m] = fmaxf(s0 + bm, 0.0f);
        h2[(rb + 1) * H2DIM + m] = fmaxf(s1 + bm, 0.0f);
        h2[(rb + 2) * H2DIM + m] = fmaxf(s2 + bm, 0.0f);
        h2[(rb + 3) * H2DIM + m] = fmaxf(s3 + bm, 0.0f);
    }
    __syncthreads();

    // layer C
    if (tid < NROWS * ODIM) {
        const int r = tid >> 1;
        const int c = tid & 1;
        float s = __ldg(&bC[c]);
#pragma unroll
        for (int m = 0; m < H2DIM; ++m)
            s = fmaf(h2[r * H2DIM + m], __ldg(&wC[m * ODIM + c]), s);
        out[(b0 + (size_t)r) * ODIM + c] = s;
    }
}

extern "C" void kernel_launch(void* const* d_in, const int* in_sizes, int n_in,
                              void* d_out, int out_size)
{
    const float* x      = (const float*)d_in[0];
    const float* w_step = (const float*)d_in[1];
    const float* b_step = (const float*)d_in[2];
    const float* wA     = (const float*)d_in[3];
    const float* bA     = (const float*)d_in[4];
    const float* wB     = (const float*)d_in[5];
    const float* bB     = (const float*)d_in[6];
    const float* wC     = (const float*)d_in[7];
    const float* bC     = (const float*)d_in[8];
    float* out          = (float*)d_out;

    pool_kernel<<<BATCH / K1_ROWS, 256>>>(x, w_step, b_step);
    mlpA_kernel<<<(BATCH / NROWS) * 2, 128>>>(wA);
    mlpB_kernel<<<BATCH / NROWS, 256>>>(bA, wB, bB, wC, bC, out);
}